// round 13
// baseline (speedup 1.0000x reference)
#include <cuda_runtime.h>

#define WARPS_PER_BLOCK 8
#define D 1024                        // feature dim (fixed by problem)
#define VEC_PER_LANE (D / 4 / 32)     // 8 float4 per lane per matrix
#define MAX_BLOCKS 8192

__device__ float g_partials[MAX_BLOCKS];
__device__ unsigned int g_count = 0;  // reset by the reducer each run

__global__ __launch_bounds__(WARPS_PER_BLOCK * 32)
void cos_loss_kernel(const float* __restrict__ a,
                     const float* __restrict__ b,
                     float* __restrict__ out,
                     int n_rows, float inv_n) {
    const int lane = threadIdx.x & 31;
    const int wid  = threadIdx.x >> 5;
    const int row  = blockIdx.x * WARPS_PER_BLOCK + wid;

    float s_ab = 0.f, s_aa = 0.f, s_bb = 0.f;

    if (row < n_rows) {
        const float4* __restrict__ a4 = reinterpret_cast<const float4*>(a) + (size_t)row * (D / 4);
        const float4* __restrict__ b4 = reinterpret_cast<const float4*>(b) + (size_t)row * (D / 4);

        float4 av[VEC_PER_LANE], bv[VEC_PER_LANE];
#pragma unroll
        for (int i = 0; i < VEC_PER_LANE; i++) {
            av[i] = a4[lane + 32 * i];
            bv[i] = b4[lane + 32 * i];
        }
#pragma unroll
        for (int i = 0; i < VEC_PER_LANE; i++) {
            s_ab = fmaf(av[i].x, bv[i].x, s_ab);
            s_ab = fmaf(av[i].y, bv[i].y, s_ab);
            s_ab = fmaf(av[i].z, bv[i].z, s_ab);
            s_ab = fmaf(av[i].w, bv[i].w, s_ab);

            s_aa = fmaf(av[i].x, av[i].x, s_aa);
            s_aa = fmaf(av[i].y, av[i].y, s_aa);
            s_aa = fmaf(av[i].z, av[i].z, s_aa);
            s_aa = fmaf(av[i].w, av[i].w, s_aa);

            s_bb = fmaf(bv[i].x, bv[i].x, s_bb);
            s_bb = fmaf(bv[i].y, bv[i].y, s_bb);
            s_bb = fmaf(bv[i].z, bv[i].z, s_bb);
            s_bb = fmaf(bv[i].w, bv[i].w, s_bb);
        }
    }

    // Warp reductions (3 values)
#pragma unroll
    for (int off = 16; off > 0; off >>= 1) {
        s_ab += __shfl_down_sync(0xFFFFFFFFu, s_ab, off);
        s_aa += __shfl_down_sync(0xFFFFFFFFu, s_aa, off);
        s_bb += __shfl_down_sync(0xFFFFFFFFu, s_bb, off);
    }

    __shared__ float sm[WARPS_PER_BLOCK];
    if (lane == 0) {
        float val = 0.f;
        if (row < n_rows) {
            const float na = fmaxf(sqrtf(s_aa), 1e-12f);
            const float nb = fmaxf(sqrtf(s_bb), 1e-12f);
            val = 1.0f - s_ab / (na * nb);
        }
        sm[wid] = val;
    }
    __syncthreads();
    // Warps 1..7 are done after this point and exit immediately.

    if (wid == 0) {
        float v = (lane < WARPS_PER_BLOCK) ? sm[lane] : 0.f;
#pragma unroll
        for (int off = 16; off > 0; off >>= 1)
            v += __shfl_down_sync(0xFFFFFFFFu, v, off);

        if (lane == 0) {
            __stcg(&g_partials[blockIdx.x], v);
            // Fire-and-forget release increment: orders the partial store
            // before the count bump, returns nothing -> no exit-path stall.
            asm volatile("red.release.gpu.global.add.u32 [%0], 1;"
                         :: "l"(&g_count) : "memory");
        }

        // Block 0's warp 0 is the designated reducer. It is resident from
        // wave 1; it spins (one block slot out of ~1184 — negligible) until
        // every block has published, then reduces deterministically.
        if (blockIdx.x == 0) {
            const unsigned int want = gridDim.x;
            if (lane == 0) {
                unsigned int c;
                do {
                    asm volatile("ld.acquire.gpu.global.u32 %0, [%1];"
                                 : "=r"(c) : "l"(&g_count) : "memory");
                } while (c < want);
            }
            __syncwarp();

            float r = 0.f;
            for (int i = lane; i < (int)want; i += 32)
                r += __ldcg(&g_partials[i]);
#pragma unroll
            for (int off = 16; off > 0; off >>= 1)
                r += __shfl_down_sync(0xFFFFFFFFu, r, off);
            if (lane == 0) {
                out[0] = r * inv_n;
                g_count = 0;   // reset for the next graph replay
            }
        }
    }
}

extern "C" void kernel_launch(void* const* d_in, const int* in_sizes, int n_in,
                              void* d_out, int out_size) {
    const float* a = (const float*)d_in[0];
    const float* b = (const float*)d_in[1];
    float* out = (float*)d_out;

    const int n_rows = in_sizes[0] / D;                                   // 16384
    const int blocks = (n_rows + WARPS_PER_BLOCK - 1) / WARPS_PER_BLOCK;  // 2048

    cos_loss_kernel<<<blocks, WARPS_PER_BLOCK * 32>>>(a, b, out, n_rows,
                                                      1.0f / (float)n_rows);
}